// round 10
// baseline (speedup 1.0000x reference)
#include <cuda_runtime.h>
#include <cstdint>
#include <math.h>

#define DIMC  512
#define NH    8
#define HD    64
#define NB    8
#define NSEQ  1024
#define QK_SCALE 0.125f

__device__ float g_q[NB * NH * NSEQ * HD];      // permuted, rounded, scaled
__device__ float g_k[NB * NH * NSEQ * HD];      // permuted, rounded
__device__ float g_v[NB * NH * NSEQ * HD];      // natural, rounded
__device__ float g_attnp[NB * NSEQ * DIMC];     // permuted, rounded
__device__ float g_xp[NB * NSEQ * DIMC];
__device__ float g_wqkvp[3 * DIMC * DIMC];
__device__ float g_wprojp[DIMC * DIMC];

__device__ __forceinline__ uint32_t f2tf(float f) {
    uint32_t r;
    asm("cvt.rna.tf32.f32 %0, %1;" : "=r"(r) : "f"(f));
    return r;
}
__device__ __forceinline__ float rndf(float f) { return __uint_as_float(f2tf(f)); }
__device__ __forceinline__ void mma8(float* d, const uint32_t* a, uint32_t b0, uint32_t b1) {
    asm volatile(
        "mma.sync.aligned.m16n8k8.row.col.f32.tf32.tf32.f32 "
        "{%0,%1,%2,%3}, {%4,%5,%6,%7}, {%8,%9}, {%0,%1,%2,%3};"
        : "+f"(d[0]), "+f"(d[1]), "+f"(d[2]), "+f"(d[3])
        : "r"(a[0]), "r"(a[1]), "r"(a[2]), "r"(a[3]), "r"(b0), "r"(b1));
}
__device__ __forceinline__ uint32_t smem_u32(const void* p) {
    uint32_t a;
    asm("{ .reg .u64 t; cvta.to.shared.u64 t, %1; cvt.u32.u64 %0, t; }" : "=r"(a) : "l"(p));
    return a;
}
#define CP16(d, s) asm volatile("cp.async.cg.shared.global [%0], [%1], 16;" :: "r"(d), "l"(s))
#define CPCOMMIT() asm volatile("cp.async.commit_group;" ::: "memory")
#define CPWAIT1()  asm volatile("cp.async.wait_group 1;" ::: "memory")
#define CPWAIT0()  asm volatile("cp.async.wait_group 0;" ::: "memory")

__device__ __forceinline__ int pslot(int d, int rot) {
    return (d & ~7) + 2 * (((d & 3) + rot) & 3) + ((d >> 2) & 1);
}

// ===========================================================================
// Pre-pass: round + permute x, qkv_w, proj_w.
// ===========================================================================
__global__ __launch_bounds__(256) void preperm(const float* __restrict__ x,
                                               const float* __restrict__ wq,
                                               const float* __restrict__ wp) {
    int idx = blockIdx.x * 256 + threadIdx.x;
    if (idx >= 10240 * 64) return;
    int row = idx >> 6, blk = idx & 63;
    const float* src; float* dst; int r;
    if (row < 8192)      { r = row;        src = x  + (size_t)r * 512; dst = g_xp    + (size_t)r * 512; }
    else if (row < 9728) { r = row - 8192; src = wq + (size_t)r * 512; dst = g_wqkvp + (size_t)r * 512; }
    else                 { r = row - 9728; src = wp + (size_t)r * 512; dst = g_wprojp + (size_t)r * 512; }
    const float4* s4 = (const float4*)(src + blk * 8);
    float4 lo = s4[0], hi = s4[1];
    int rot = (r >> 2) & 3;
    float t[8];
    t[2 * ((0 + rot) & 3)] = rndf(lo.x); t[2 * ((0 + rot) & 3) + 1] = rndf(hi.x);
    t[2 * ((1 + rot) & 3)] = rndf(lo.y); t[2 * ((1 + rot) & 3) + 1] = rndf(hi.y);
    t[2 * ((2 + rot) & 3)] = rndf(lo.z); t[2 * ((2 + rot) & 3) + 1] = rndf(hi.z);
    t[2 * ((3 + rot) & 3)] = rndf(lo.w); t[2 * ((3 + rot) & 3) + 1] = rndf(hi.w);
    float4* d4 = (float4*)(dst + blk * 8);
    d4[0] = make_float4(t[0], t[1], t[2], t[3]);
    d4[1] = make_float4(t[4], t[5], t[6], t[7]);
}

// ===========================================================================
// GEMM: CTA 128x128, 256 thr, 8 warps (2x4), warp tile 64x32, BK=32,
// 3-stage cp.async pipeline, ONE syncthreads per chunk.
// ===========================================================================
#define GP 40
#define GSTAGE (2 * 128 * GP)
#define GEMM_SMEM (3 * GSTAGE * 4)          // 122880 B

__global__ __launch_bounds__(256) void mma_gemm(const float* __restrict__ Bvec,
                                                float* __restrict__ Out,
                                                int mode) {
    extern __shared__ float sm[];
    const uint32_t sbase = smem_u32(sm);
    const int tid = threadIdx.x, wid = tid >> 5, lane = tid & 31;
    const int g = lane >> 2, th = lane & 3;
    const int wm = wid >> 2, wn = wid & 3;
    const int bm = blockIdx.x * 128, bn = blockIdx.y * 128;

    const float* Ap = mode ? g_attnp : g_xp;
    const float* Wp = mode ? g_wprojp : g_wqkvp;

    const int lrow = tid & 127, side = tid >> 7;
    const float* gsrc = side ? (Wp + (size_t)(bn + lrow) * 512)
                             : (Ap + (size_t)(bm + lrow) * 512);
    const uint32_t dst0 = sbase + (uint32_t)(side * 128 * GP + lrow * GP) * 4;

    int offA0[4], offA1[4], offB[4];
#pragma unroll
    for (int ma = 0; ma < 4; ma++) {
        int ra = wm * 64 + ma * 16 + g;
        offA0[ma] = ra * GP + 2 * ((th + (ra >> 2)) & 3);
        int rb = ra + 8;
        offA1[ma] = rb * GP + 2 * ((th + (rb >> 2)) & 3);
    }
#pragma unroll
    for (int nb = 0; nb < 4; nb++) {
        int rc = wn * 32 + nb * 8 + g;
        offB[nb] = rc * GP + 2 * ((th + (rc >> 2)) & 3);
    }

    float acc[4][4][4];
#pragma unroll
    for (int i = 0; i < 4; i++)
#pragma unroll
        for (int j = 0; j < 4; j++)
#pragma unroll
            for (int q = 0; q < 4; q++) acc[i][j][q] = 0.0f;

#define G_ISSUE(I, ST)                                                    \
    {                                                                     \
        uint32_t _d = dst0 + (uint32_t)(ST) * (GSTAGE * 4);               \
        const float* _s = gsrc + (I) * 32;                                \
        _Pragma("unroll")                                                 \
        for (int c = 0; c < 8; c++) CP16(_d + c * 16, _s + c * 4);        \
        CPCOMMIT();                                                       \
    }

    G_ISSUE(0, 0);
    G_ISSUE(1, 1);

    int st = 0, stn = 2;     // stage of chunk i; stage for chunk i+2
    for (int i = 0; i < 16; i++) {
        if (i < 15) CPWAIT1(); else CPWAIT0();
        __syncthreads();
        if (i + 2 < 16) G_ISSUE(i + 2, stn);
        const float* A = sm + st * GSTAGE;
        const float* B = A + 128 * GP;
#pragma unroll
        for (int s = 0; s < 4; s++) {
            uint32_t Af[4][4];
#pragma unroll
            for (int ma = 0; ma < 4; ma++) {
                float2 lo = *(const float2*)(A + offA0[ma] + 8 * s);
                float2 hi = *(const float2*)(A + offA1[ma] + 8 * s);
                Af[ma][0] = __float_as_uint(lo.x); Af[ma][1] = __float_as_uint(hi.x);
                Af[ma][2] = __float_as_uint(lo.y); Af[ma][3] = __float_as_uint(hi.y);
            }
#pragma unroll
            for (int nb = 0; nb < 4; nb++) {
                float2 bv = *(const float2*)(B + offB[nb] + 8 * s);
                uint32_t b0 = __float_as_uint(bv.x), b1 = __float_as_uint(bv.y);
#pragma unroll
                for (int ma = 0; ma < 4; ma++) mma8(acc[ma][nb], Af[ma], b0, b1);
            }
        }
        st = (st + 1 == 3) ? 0 : st + 1;
        stn = (stn + 1 == 3) ? 0 : stn + 1;
    }

#pragma unroll
    for (int ma = 0; ma < 4; ma++) {
#pragma unroll
        for (int nb = 0; nb < 4; nb++) {
            int r0 = bm + wm * 64 + ma * 16 + g;
            int cg = bn + wn * 32 + nb * 8 + 2 * th;
#pragma unroll
            for (int e = 0; e < 2; e++) {
                int rr = r0 + e * 8;
                float v0 = acc[ma][nb][2 * e], v1 = acc[ma][nb][2 * e + 1];
                if (mode == 0) {
                    int bb = rr >> 10, n = rr & 1023;
                    int which = cg >> 9, hh = (cg >> 6) & 7, dd = cg & 63;
                    size_t off = (((size_t)(bb * NH + hh)) * NSEQ + n) * HD;
                    int rot = (n >> 2) & 3;
                    if (which == 0) {
                        g_q[off + pslot(dd, rot)]     = rndf(v0 * QK_SCALE);
                        g_q[off + pslot(dd + 1, rot)] = rndf(v1 * QK_SCALE);
                    } else if (which == 1) {
                        g_k[off + pslot(dd, rot)]     = rndf(v0);
                        g_k[off + pslot(dd + 1, rot)] = rndf(v1);
                    } else {
                        float2 o; o.x = rndf(v0); o.y = rndf(v1);
                        *(float2*)(g_v + off + dd) = o;
                    }
                } else {
                    float2 bv = *(const float2*)(Bvec + cg);
                    float2 o; o.x = v0 + bv.x; o.y = v1 + bv.y;
                    *(float2*)(Out + (size_t)rr * 512 + cg) = o;
                }
            }
        }
    }
}

// ===========================================================================
// Flash attention: 3-stage pipeline (K, V, bias all cp.async), 1 sync/tile.
// Stage layout (floats): K[64*72] @0, V[64*72] @4608, bias[128*72] @9216.
// ===========================================================================
#define AKP 72
#define ASTG 18432                          // floats per stage
#define ATT_SMEM (3 * ASTG * 4)             // 221184 B

__global__ __launch_bounds__(256) void attn_mma(const float* __restrict__ bias) {
    extern __shared__ float sm[];
    const uint32_t sbase = smem_u32(sm);
    const int qt = blockIdx.x, h = blockIdx.y, b = blockIdx.z;
    const int tid = threadIdx.x, wid = tid >> 5, lane = tid & 31;
    const int g = lane >> 2, th = lane & 3;

    const size_t bh = (size_t)(b * NH + h);
    const float* Kg = g_k + bh * NSEQ * HD;
    const float* Vg = g_v + bh * NSEQ * HD;

    const int qrow = qt * 128 + wid * 16 + g;
    const float* Q0 = g_q + (bh * NSEQ + qrow) * HD;
    const float* Q1 = Q0 + 8 * HD;
    const int rq0 = 2 * ((th + (qrow >> 2)) & 3);
    const int rq1 = 2 * ((th + ((qrow + 8) >> 2)) & 3);
    uint32_t qa[8][4];
#pragma unroll
    for (int s = 0; s < 8; s++) {
        float2 a0 = *(const float2*)(Q0 + 8 * s + rq0);
        float2 a1 = *(const float2*)(Q1 + 8 * s + rq1);
        qa[s][0] = __float_as_uint(a0.x); qa[s][2] = __float_as_uint(a0.y);
        qa[s][1] = __float_as_uint(a1.x); qa[s][3] = __float_as_uint(a1.y);
    }

    int offK[8];
#pragma unroll
    for (int na = 0; na < 8; na++) {
        int rc = na * 8 + g;
        offK[na] = rc * AKP + 2 * ((th + (rc >> 2)) & 3);
    }

    float O[8][4];
#pragma unroll
    for (int na = 0; na < 8; na++)
#pragma unroll
        for (int q = 0; q < 4; q++) O[na][q] = 0.0f;
    float mrow[2] = {-INFINITY, -INFINITY};
    float lrow[2] = {0.0f, 0.0f};

    // cp.async mapping: KV: row=tid>>2 (0..63), quarter=tid&3
    //                   bias: row=tid>>1 (0..127), half=(tid&1)*32
    const int arow = tid >> 2, aq = tid & 3;
    const int brow = tid >> 1, bcol = (tid & 1) * 32;
    const float* biasg = bias + ((size_t)h * NSEQ + (size_t)qt * 128 + brow) * NSEQ + bcol;

#define A_ISSUE(T, ST)                                                        \
    {                                                                         \
        uint32_t _sb = sbase + (uint32_t)(ST) * (ASTG * 4);                   \
        uint32_t _kd = _sb + (arow * AKP + aq * 16) * 4;                      \
        uint32_t _vd = _kd + 4608 * 4;                                        \
        const float* _ks = Kg + ((size_t)((T) * 64 + arow)) * 64 + aq * 16;   \
        const float* _vs = Vg + ((size_t)((T) * 64 + arow)) * 64 + aq * 16;   \
        _Pragma("unroll")                                                     \
        for (int c = 0; c < 4; c++) {                                         \
            CP16(_kd + c * 16, _ks + c * 4);                                  \
            CP16(_vd + c * 16, _vs + c * 4);                                  \
        }                                                                     \
        uint32_t _bd = _sb + (9216 + brow * AKP + bcol) * 4;                  \
        const float* _bs = biasg + (T) * 64;                                  \
        _Pragma("unroll")                                                     \
        for (int c = 0; c < 8; c++) CP16(_bd + c * 16, _bs + c * 4);          \
        CPCOMMIT();                                                           \
    }

    A_ISSUE(0, 0);
    A_ISSUE(1, 1);

    int st = 0, stn = 2;
    for (int t = 0; t < 16; t++) {
        if (t < 15) CPWAIT1(); else CPWAIT0();
        __syncthreads();
        if (t + 2 < 16) A_ISSUE(t + 2, stn);
        const float* Ks = sm + st * ASTG;
        const float* Vs = Ks + 4608;
        const float* Bs = Ks + 9216;

        // S = Q K^T
        float S[8][4];
#pragma unroll
        for (int na = 0; na < 8; na++)
#pragma unroll
            for (int q = 0; q < 4; q++) S[na][q] = 0.0f;
#pragma unroll
        for (int s = 0; s < 8; s++) {
#pragma unroll
            for (int na = 0; na < 8; na++) {
                float2 bv = *(const float2*)(Ks + offK[na] + 8 * s);
                mma8(S[na], qa[s], __float_as_uint(bv.x), __float_as_uint(bv.y));
            }
        }

        // + bias from smem
        const float* bs0 = Bs + (wid * 16 + g) * AKP + 2 * th;
        const float* bs1 = bs0 + 8 * AKP;
#pragma unroll
        for (int na = 0; na < 8; na++) {
            float2 b0v = *(const float2*)(bs0 + na * 8);
            float2 b1v = *(const float2*)(bs1 + na * 8);
            S[na][0] += b0v.x; S[na][1] += b0v.y;
            S[na][2] += b1v.x; S[na][3] += b1v.y;
        }

        // online softmax
#pragma unroll
        for (int e = 0; e < 2; e++) {
            float mx = -INFINITY;
#pragma unroll
            for (int na = 0; na < 8; na++)
                mx = fmaxf(mx, fmaxf(S[na][2 * e], S[na][2 * e + 1]));
            mx = fmaxf(mx, __shfl_xor_sync(0xffffffffu, mx, 1));
            mx = fmaxf(mx, __shfl_xor_sync(0xffffffffu, mx, 2));
            float mn = fmaxf(mrow[e], mx);
            float al = __expf(mrow[e] - mn);
            mrow[e] = mn;
            float ls = 0.0f;
#pragma unroll
            for (int na = 0; na < 8; na++) {
                S[na][2 * e]     = __expf(S[na][2 * e] - mn);
                S[na][2 * e + 1] = __expf(S[na][2 * e + 1] - mn);
                ls += S[na][2 * e] + S[na][2 * e + 1];
            }
            ls += __shfl_xor_sync(0xffffffffu, ls, 1);
            ls += __shfl_xor_sync(0xffffffffu, ls, 2);
            lrow[e] = lrow[e] * al + ls;
#pragma unroll
            for (int na = 0; na < 8; na++) { O[na][2 * e] *= al; O[na][2 * e + 1] *= al; }
        }

#pragma unroll
        for (int na = 0; na < 8; na++)
#pragma unroll
            for (int q = 0; q < 4; q++) S[na][q] = __uint_as_float(f2tf(S[na][q]));

        // O += P V (P re-fragmented via quad shuffles; V frags 2x LDS.32)
        const int src0 = (lane & ~3) | (th >> 1);
        const int src2 = src0 + 2;
        const bool odd = (th & 1);
#pragma unroll
        for (int s = 0; s < 8; s++) {
            float x0 = __shfl_sync(0xffffffffu, S[s][0], src0);
            float x1 = __shfl_sync(0xffffffffu, S[s][1], src0);
            float y0 = __shfl_sync(0xffffffffu, S[s][2], src0);
            float y1 = __shfl_sync(0xffffffffu, S[s][3], src0);
            float z0 = __shfl_sync(0xffffffffu, S[s][0], src2);
            float z1 = __shfl_sync(0xffffffffu, S[s][1], src2);
            float w0 = __shfl_sync(0xffffffffu, S[s][2], src2);
            float w1 = __shfl_sync(0xffffffffu, S[s][3], src2);
            uint32_t a[4];
            a[0] = __float_as_uint(odd ? x1 : x0);
            a[1] = __float_as_uint(odd ? y1 : y0);
            a[2] = __float_as_uint(odd ? z1 : z0);
            a[3] = __float_as_uint(odd ? w1 : w0);
            const float* vr0 = Vs + (8 * s + th) * AKP + g;
            const float* vr1 = Vs + (8 * s + th + 4) * AKP + g;
#pragma unroll
            for (int na = 0; na < 8; na++) {
                uint32_t b0 = __float_as_uint(vr0[na * 8]);
                uint32_t b1 = __float_as_uint(vr1[na * 8]);
                mma8(O[na], a, b0, b1);
            }
        }
        st = (st + 1 == 3) ? 0 : st + 1;
        stn = (stn + 1 == 3) ? 0 : stn + 1;
    }

    const float i0 = 1.0f / lrow[0];
    const float i1 = 1.0f / lrow[1];
    const int rot0 = (qrow >> 2) & 3;
    const int rot1 = ((qrow + 8) >> 2) & 3;
    float* ob0 = g_attnp + ((size_t)b * NSEQ + qrow) * DIMC;
    float* ob1 = ob0 + (size_t)8 * DIMC;
#pragma unroll
    for (int na = 0; na < 8; na++) {
        int c = h * 64 + na * 8 + 2 * th;
        ob0[pslot(c, rot0)]     = rndf(O[na][0] * i0);
        ob0[pslot(c + 1, rot0)] = rndf(O[na][1] * i0);
        ob1[pslot(c, rot1)]     = rndf(O[na][2] * i1);
        ob1[pslot(c + 1, rot1)] = rndf(O[na][3] * i1);
    }
}

extern "C" void kernel_launch(void* const* d_in, const int* in_sizes, int n_in,
                              void* d_out, int out_size) {
    const float* x      = (const float*)d_in[0];
    const float* rpe    = (const float*)d_in[1];
    const float* qkv_w  = (const float*)d_in[2];
    const float* proj_w = (const float*)d_in[3];
    const float* proj_b = (const float*)d_in[4];
    float* out = (float*)d_out;

    preperm<<<(10240 * 64 + 255) / 256, 256>>>(x, qkv_w, proj_w);
    cudaFuncSetAttribute(mma_gemm, cudaFuncAttributeMaxDynamicSharedMemorySize, GEMM_SMEM);
    cudaFuncSetAttribute(attn_mma, cudaFuncAttributeMaxDynamicSharedMemorySize, ATT_SMEM);
    mma_gemm<<<dim3(64, 12), 256, GEMM_SMEM>>>(nullptr, nullptr, 0);
    attn_mma<<<dim3(8, 8, 8), 256, ATT_SMEM>>>(rpe);
    mma_gemm<<<dim3(64, 4), 256, GEMM_SMEM>>>(proj_b, out, 1);
}

// round 11
// speedup vs baseline: 2.3346x; 2.3346x over previous
#include <cuda_runtime.h>
#include <cuda_fp16.h>
#include <cstdint>
#include <math.h>

#define DIMC  512
#define NH    8
#define HD    64
#define NB    8
#define NSEQ  1024
#define QK_SCALE 0.125f

// fp16 scratch, pair-permuted per 16-block: [0,1,8,9,2,3,10,11,4,5,12,13,6,7,14,15]
__device__ __half g_q[NB * NH * NSEQ * HD];      // [bh][n][d]  perm, *0.125
__device__ __half g_k[NB * NH * NSEQ * HD];      // [bh][n][d]  perm
__device__ __half g_vt[NB * NH * HD * NSEQ];     // [bh][d][kv] perm over kv
__device__ __half g_attnp[NB * NSEQ * DIMC];     // [b*n][c]    perm
__device__ __half g_xp[NB * NSEQ * DIMC];
__device__ __half g_wqkvp[3 * DIMC * DIMC];
__device__ __half g_wprojp[DIMC * DIMC];

__device__ __forceinline__ int perm16(int d) {   // d in [0,16)
    return (((d & 7) >> 1) << 2) + (((d >> 3) & 1) << 1) + (d & 1);
}
__device__ __forceinline__ uint32_t packh(float lo, float hi) {
    __half2 h = __floats2half2_rn(lo, hi);
    return *(uint32_t*)&h;
}
__device__ __forceinline__ void mma16(float* d, const uint32_t* a, uint32_t b0, uint32_t b1) {
    asm volatile(
        "mma.sync.aligned.m16n8k16.row.col.f32.f16.f16.f32 "
        "{%0,%1,%2,%3}, {%4,%5,%6,%7}, {%8,%9}, {%0,%1,%2,%3};"
        : "+f"(d[0]), "+f"(d[1]), "+f"(d[2]), "+f"(d[3])
        : "r"(a[0]), "r"(a[1]), "r"(a[2]), "r"(a[3]), "r"(b0), "r"(b1));
}
__device__ __forceinline__ uint32_t smem_u32(const void* p) {
    uint32_t a;
    asm("{ .reg .u64 t; cvta.to.shared.u64 t, %1; cvt.u32.u64 %0, t; }" : "=r"(a) : "l"(p));
    return a;
}
#define CP16(d, s) asm volatile("cp.async.cg.shared.global [%0], [%1], 16;" :: "r"(d), "l"(s))
#define CPCOMMIT() asm volatile("cp.async.commit_group;" ::: "memory")
#define CPWAIT1()  asm volatile("cp.async.wait_group 1;" ::: "memory")
#define CPWAIT0()  asm volatile("cp.async.wait_group 0;" ::: "memory")

// ===========================================================================
// Pre-pass: fp32 -> fp16 permuted. One thread per 16-element block.
// rows: x 8192 | qkv_w 1536 | proj_w 512  (each 512 wide = 32 blocks)
// ===========================================================================
__global__ __launch_bounds__(256) void preperm(const float* __restrict__ x,
                                               const float* __restrict__ wq,
                                               const float* __restrict__ wp) {
    int idx = blockIdx.x * 256 + threadIdx.x;
    if (idx >= 10240 * 32) return;
    int row = idx >> 5, blk = idx & 31;
    const float* src; __half* dst; int r;
    if (row < 8192)      { r = row;        src = x  + (size_t)r * 512; dst = g_xp    + (size_t)r * 512; }
    else if (row < 9728) { r = row - 8192; src = wq + (size_t)r * 512; dst = g_wqkvp + (size_t)r * 512; }
    else                 { r = row - 9728; src = wp + (size_t)r * 512; dst = g_wprojp + (size_t)r * 512; }
    float f[16];
    const float4* s4 = (const float4*)(src + blk * 16);
#pragma unroll
    for (int i = 0; i < 4; i++) { float4 v = s4[i]; f[4*i] = v.x; f[4*i+1] = v.y; f[4*i+2] = v.z; f[4*i+3] = v.w; }
    uint32_t u[8];
#pragma unroll
    for (int k = 0; k < 8; k++) {
        int e = 2 * (k >> 1) + 8 * (k & 1);
        u[k] = packh(f[e], f[e + 1]);
    }
    uint4* d4 = (uint4*)(dst + blk * 16);
    d4[0] = make_uint4(u[0], u[1], u[2], u[3]);
    d4[1] = make_uint4(u[4], u[5], u[6], u[7]);
}

// ===========================================================================
// fp16 GEMM: CTA 128x128, 256 thr, 8 warps (2x4), warp tile 64x32,
// BK=32 halfs, 2-stage cp.async. Smem pitch 80 halfs (160B) -> conflict-free.
// mode 0: A=g_xp, B=g_wqkvp -> scatter q/k (perm) + v (transposed perm)
// mode 1: A=g_attnp, B=g_wprojp -> +bias, f32 Out
// ===========================================================================
#define GP 80                                // halfs
#define GSTAGE_B (256 * GP * 2)              // bytes per stage = 40960
#define GEMM_SMEM (2 * GSTAGE_B)             // 81920

__global__ __launch_bounds__(256, 2) void mma_gemm(const float* __restrict__ Bvec,
                                                   float* __restrict__ Out,
                                                   int mode) {
    extern __shared__ __half smh[];
    const uint32_t sbase = smem_u32(smh);
    const int tid = threadIdx.x, wid = tid >> 5, lane = tid & 31;
    const int g = lane >> 2, th = lane & 3;
    const int wm = wid >> 2, wn = wid & 3;
    const int bm = blockIdx.x * 128, bn = blockIdx.y * 128;

    const __half* Ap = mode ? g_attnp : g_xp;
    const __half* Wp = mode ? g_wprojp : g_wqkvp;
    const int lrow = tid & 127, side = tid >> 7;
    const __half* gsrc = side ? (Wp + (size_t)(bn + lrow) * 512)
                              : (Ap + (size_t)(bm + lrow) * 512);
    const uint32_t dst0 = sbase + (uint32_t)((side * 128 + lrow) * GP) * 2;

    int offA0[4], offA1[4], offB[4];
#pragma unroll
    for (int ma = 0; ma < 4; ma++) {
        int ra = wm * 64 + ma * 16 + g;
        offA0[ma] = ra * GP + 4 * th;
        offA1[ma] = (ra + 8) * GP + 4 * th;
    }
#pragma unroll
    for (int nb = 0; nb < 4; nb++) {
        int rc = 128 * GP + (wn * 32 + nb * 8 + g) * GP + 4 * th;
        offB[nb] = rc;
    }

    float acc[4][4][4];
#pragma unroll
    for (int i = 0; i < 4; i++)
#pragma unroll
        for (int j = 0; j < 4; j++)
#pragma unroll
            for (int q = 0; q < 4; q++) acc[i][j][q] = 0.0f;

#define G_ISSUE(I)                                                        \
    {                                                                     \
        uint32_t _d = dst0 + ((I) & 1) * GSTAGE_B;                        \
        const __half* _s = gsrc + (I) * 32;                               \
        _Pragma("unroll")                                                 \
        for (int c = 0; c < 4; c++) CP16(_d + c * 16, _s + c * 8);        \
        CPCOMMIT();                                                       \
    }

    G_ISSUE(0);
    G_ISSUE(1);

    for (int i = 0; i < 16; i++) {
        if (i < 15) CPWAIT1(); else CPWAIT0();
        __syncthreads();
        const __half* S0 = smh + (i & 1) * (GSTAGE_B / 2);
#pragma unroll
        for (int s = 0; s < 2; s++) {
            uint32_t Af[4][4];
#pragma unroll
            for (int ma = 0; ma < 4; ma++) {
                uint2 lo = *(const uint2*)(S0 + offA0[ma] + 16 * s);
                uint2 hi = *(const uint2*)(S0 + offA1[ma] + 16 * s);
                Af[ma][0] = lo.x; Af[ma][1] = hi.x; Af[ma][2] = lo.y; Af[ma][3] = hi.y;
            }
#pragma unroll
            for (int nb = 0; nb < 4; nb++) {
                uint2 bv = *(const uint2*)(S0 + offB[nb] + 16 * s);
#pragma unroll
                for (int ma = 0; ma < 4; ma++) mma16(acc[ma][nb], Af[ma], bv.x, bv.y);
            }
        }
        __syncthreads();
        if (i + 2 < 16) G_ISSUE(i + 2);
    }

#pragma unroll
    for (int ma = 0; ma < 4; ma++) {
#pragma unroll
        for (int nb = 0; nb < 4; nb++) {
            int r0 = bm + wm * 64 + ma * 16 + g;
            int cg = bn + wn * 32 + nb * 8 + 2 * th;
#pragma unroll
            for (int e = 0; e < 2; e++) {
                int rr = r0 + e * 8;
                float v0 = acc[ma][nb][2 * e], v1 = acc[ma][nb][2 * e + 1];
                if (mode == 0) {
                    int bb = rr >> 10, n = rr & 1023;
                    int which = cg >> 9, hh = (cg >> 6) & 7, dd = cg & 63;
                    size_t bh = (size_t)(bb * NH + hh);
                    if (which == 0) {
                        size_t off = (bh * NSEQ + n) * HD + (dd & ~15) + perm16(dd & 15);
                        *(__half2*)(g_q + off) = __floats2half2_rn(v0 * QK_SCALE, v1 * QK_SCALE);
                    } else if (which == 1) {
                        size_t off = (bh * NSEQ + n) * HD + (dd & ~15) + perm16(dd & 15);
                        *(__half2*)(g_k + off) = __floats2half2_rn(v0, v1);
                    } else {
                        size_t vb = (bh * HD + dd) * NSEQ + (n & ~15) + perm16(n & 15);
                        g_vt[vb]        = __float2half_rn(v0);
                        g_vt[vb + NSEQ] = __float2half_rn(v1);
                    }
                } else {
                    float2 bv = *(const float2*)(Bvec + cg);
                    float2 o; o.x = v0 + bv.x; o.y = v1 + bv.y;
                    *(float2*)(Out + (size_t)rr * 512 + cg) = o;
                }
            }
        }
    }
}

// ===========================================================================
// fp16 flash attention. Grid (8 qt, 8 h, 8 b), 256 thr, 8 warps x 16 q-rows.
// K [kv][d] + Vt [d][kv] tiles, 2-stage cp.async, pitch 80 halfs.
// PV A-fragments are direct repacks of S registers (no shuffles).
// ===========================================================================
#define AKP 80
#define ASTG_B (128 * AKP * 2)               // K(64 rows)+V(64 rows) = 20480 B
#define ATT_SMEM (2 * ASTG_B)                // 40960 B

__global__ __launch_bounds__(256) void attn_mma(const float* __restrict__ bias) {
    extern __shared__ __half smh[];
    const uint32_t sbase = smem_u32(smh);
    const int qt = blockIdx.x, h = blockIdx.y, b = blockIdx.z;
    const int tid = threadIdx.x, wid = tid >> 5, lane = tid & 31;
    const int g = lane >> 2, th = lane & 3;

    const size_t bh = (size_t)(b * NH + h);
    const __half* Kg = g_k + bh * NSEQ * HD;
    const __half* Vg = g_vt + bh * HD * NSEQ;

    // Q fragments: 4 k-steps of 16 over HD=64
    const int qrow = qt * 128 + wid * 16 + g;
    const __half* Q0 = g_q + (bh * NSEQ + qrow) * HD;
    const __half* Q1 = Q0 + 8 * HD;
    uint32_t qa[4][4];
#pragma unroll
    for (int s = 0; s < 4; s++) {
        uint2 lo = *(const uint2*)(Q0 + 16 * s + 4 * th);
        uint2 hi = *(const uint2*)(Q1 + 16 * s + 4 * th);
        qa[s][0] = lo.x; qa[s][1] = hi.x; qa[s][2] = lo.y; qa[s][3] = hi.y;
    }

    int offK[8], offV[8];
#pragma unroll
    for (int na = 0; na < 8; na++) {
        offK[na] = (na * 8 + g) * AKP + 4 * th;
        offV[na] = 64 * AKP + (na * 8 + g) * AKP + 4 * th;
    }

    float O[8][4];
#pragma unroll
    for (int na = 0; na < 8; na++)
#pragma unroll
        for (int q = 0; q < 4; q++) O[na][q] = 0.0f;
    float mrow[2] = {-INFINITY, -INFINITY};
    float lrow[2] = {0.0f, 0.0f};

    const int arow = tid >> 2, aq = tid & 3;

#define A_ISSUE(T)                                                            \
    {                                                                         \
        uint32_t _sb = sbase + ((T) & 1) * ASTG_B;                            \
        uint32_t _kd = _sb + (arow * AKP) * 2 + aq * 32;                      \
        uint32_t _vd = _kd + 64 * AKP * 2;                                    \
        const __half* _ks = Kg + ((size_t)((T) * 64 + arow)) * 64 + aq * 16;  \
        const __half* _vs = Vg + (size_t)arow * NSEQ + (T) * 64 + aq * 16;    \
        CP16(_kd, _ks); CP16(_kd + 16, _ks + 8);                              \
        CP16(_vd, _vs); CP16(_vd + 16, _vs + 8);                              \
        CPCOMMIT();                                                           \
    }

    A_ISSUE(0);

    for (int t = 0; t < 16; t++) {
        if (t < 15) { A_ISSUE(t + 1); CPWAIT1(); } else { CPWAIT0(); }
        __syncthreads();
        const __half* Ks = smh + (t & 1) * (ASTG_B / 2);

        // S = Q K^T  (16 x 64 per warp): 8 na x 4 s mma
        float S[8][4];
#pragma unroll
        for (int na = 0; na < 8; na++)
#pragma unroll
            for (int q = 0; q < 4; q++) S[na][q] = 0.0f;
#pragma unroll
        for (int s = 0; s < 4; s++) {
#pragma unroll
            for (int na = 0; na < 8; na++) {
                uint2 bv = *(const uint2*)(Ks + offK[na] + 16 * s);
                mma16(S[na], qa[s], bv.x, bv.y);
            }
        }

        // + bias (direct LDG)
        const float* bp0 = bias + ((size_t)h * NSEQ + qrow) * NSEQ + t * 64 + 2 * th;
        const float* bp1 = bp0 + 8 * NSEQ;
#pragma unroll
        for (int na = 0; na < 8; na++) {
            float2 b0v = *(const float2*)(bp0 + na * 8);
            float2 b1v = *(const float2*)(bp1 + na * 8);
            S[na][0] += b0v.x; S[na][1] += b0v.y;
            S[na][2] += b1v.x; S[na][3] += b1v.y;
        }

        // online softmax (rows e=0: regs 0,1; e=1: regs 2,3)
#pragma unroll
        for (int e = 0; e < 2; e++) {
            float mx = -INFINITY;
#pragma unroll
            for (int na = 0; na < 8; na++)
                mx = fmaxf(mx, fmaxf(S[na][2 * e], S[na][2 * e + 1]));
            mx = fmaxf(mx, __shfl_xor_sync(0xffffffffu, mx, 1));
            mx = fmaxf(mx, __shfl_xor_sync(0xffffffffu, mx, 2));
            float mn = fmaxf(mrow[e], mx);
            float al = __expf(mrow[e] - mn);
            mrow[e] = mn;
            float ls = 0.0f;
#pragma unroll
            for (int na = 0; na < 8; na++) {
                S[na][2 * e]     = __expf(S[na][2 * e] - mn);
                S[na][2 * e + 1] = __expf(S[na][2 * e + 1] - mn);
                ls += S[na][2 * e] + S[na][2 * e + 1];
            }
            ls += __shfl_xor_sync(0xffffffffu, ls, 1);
            ls += __shfl_xor_sync(0xffffffffu, ls, 2);
            lrow[e] = lrow[e] * al + ls;
#pragma unroll
            for (int na = 0; na < 8; na++) { O[na][2 * e] *= al; O[na][2 * e + 1] *= al; }
        }

        // O += P V : A-frags = direct repack of own S regs; V frags LDS.64
#pragma unroll
        for (int s = 0; s < 4; s++) {
            uint32_t a[4];
            a[0] = packh(S[2 * s][0],     S[2 * s][1]);
            a[1] = packh(S[2 * s][2],     S[2 * s][3]);
            a[2] = packh(S[2 * s + 1][0], S[2 * s + 1][1]);
            a[3] = packh(S[2 * s + 1][2], S[2 * s + 1][3]);
#pragma unroll
            for (int na = 0; na < 8; na++) {
                uint2 bv = *(const uint2*)(Ks + offV[na] + 16 * s);
                mma16(O[na], a, bv.x, bv.y);
            }
        }
        __syncthreads();
    }

    // normalize + write g_attnp (fp16 permuted)
    const float i0 = 1.0f / lrow[0];
    const float i1 = 1.0f / lrow[1];
    __half* ob0 = g_attnp + ((size_t)b * NSEQ + qrow) * DIMC;
    __half* ob1 = ob0 + (size_t)8 * DIMC;
#pragma unroll
    for (int na = 0; na < 8; na++) {
        int c = h * 64 + na * 8 + 2 * th;
        int cp = (c & ~15) + perm16(c & 15);
        *(__half2*)(ob0 + cp) = __floats2half2_rn(O[na][0] * i0, O[na][1] * i0);
        *(__half2*)(ob1 + cp) = __floats2half2_rn(O[na][2] * i1, O[na][3] * i1);
    }
}

extern "C" void kernel_launch(void* const* d_in, const int* in_sizes, int n_in,
                              void* d_out, int out_size) {
    const float* x      = (const float*)d_in[0];
    const float* rpe    = (const float*)d_in[1];
    const float* qkv_w  = (const float*)d_in[2];
    const float* proj_w = (const float*)d_in[3];
    const float* proj_b = (const float*)d_in[4];
    float* out = (float*)d_out;

    preperm<<<(10240 * 32 + 255) / 256, 256>>>(x, qkv_w, proj_w);
    cudaFuncSetAttribute(mma_gemm, cudaFuncAttributeMaxDynamicSharedMemorySize, GEMM_SMEM);
    mma_gemm<<<dim3(64, 12), 256, GEMM_SMEM>>>(nullptr, nullptr, 0);
    attn_mma<<<dim3(8, 8, 8), 256, ATT_SMEM>>>(rpe);
    mma_gemm<<<dim3(64, 4), 256, GEMM_SMEM>>>(proj_b, out, 1);
}